// round 10
// baseline (speedup 1.0000x reference)
#include <cuda_runtime.h>
#include <cstdint>

#define NB 64
#define NT 256
#define NC 2048
#define NH 512
#define NO 11
#define THRESH 1.0f
#define LEAKV  0.003f
#define OLEAK  0.0015f
#define DELTA  2e-3f

// Scratch (static device allocations — allowed)
__device__ float    g_Iin[NB * NT * NH];     // [b][t][h]
__device__ float    g_WrecT[NH * NH];        // [j][h]
__device__ int      g_doneY[128];            // per-y-tile counters (->4)
__device__ uint32_t g_spk[NB][NT][16];       // spike bitmaps (h bit in word h>>5)
__device__ int      g_flagged[NB * NH];      // per-neuron flag (dedup)
__device__ int      g_fcnt[NB];              // flagged count per batch
__device__ int      g_flist[NB][NH];         // flagged neuron list per batch
__device__ int      g_dirty[NB];             // batch needs exact redo

// ---------------------------------------------------------------------------
__device__ __forceinline__ float tf32_rna(float x) {
    float r;
    asm("cvt.rna.tf32.f32 %0, %1;" : "=f"(r) : "f"(x));
    return r;
}
__device__ __forceinline__ void mma_tf32(float* d, const uint32_t* a, const uint32_t* b) {
    asm volatile(
        "mma.sync.aligned.m16n8k8.row.col.f32.tf32.tf32.f32 "
        "{%0,%1,%2,%3}, {%4,%5,%6,%7}, {%8,%9}, {%0,%1,%2,%3};"
        : "+f"(d[0]), "+f"(d[1]), "+f"(d[2]), "+f"(d[3])
        : "r"(a[0]), "r"(a[1]), "r"(a[2]), "r"(a[3]), "r"(b[0]), "r"(b[1]));
}

// ---------------------------------------------------------------------------
// Prep: zero all control state + transpose w_rec
// ---------------------------------------------------------------------------
__global__ void prep_kernel(const float* __restrict__ w_rec) {
    int idx = blockIdx.x * blockDim.x + threadIdx.x;
    if (idx < NB * NH) g_flagged[idx] = 0;
    if (idx < 128) g_doneY[idx] = 0;
    if (idx < NB) { g_fcnt[idx] = 0; g_dirty[idx] = 0; }
    if (idx < NH * NH) {
        int h = idx / NH, j = idx % NH;
        g_WrecT[j * NH + h] = w_rec[idx];
    }
}

// ---------------------------------------------------------------------------
// Fused: blocks 0..511 do one 128x128 3xTF32 mma GEMM tile (even y first),
// blocks 0..63 then morph into the speculative SNN for batch blk.
// ---------------------------------------------------------------------------
#define BKI  16
#define SPAD 136

union SmemU {
    struct { float sA[2][BKI][SPAD]; float sB[2][BKI][SPAD]; } g;
    struct {
        int   list[NH]; int wcnt[16]; int base[16]; int total;
        float w2t[NH * 12];
    } s;
};

__global__ __launch_bounds__(256) void fused_kernel(
    const float* __restrict__ A,    // x  [M,K]
    const float* __restrict__ W,    // w1 [N,K]
    const float* __restrict__ w2,   // [O,H]
    float* __restrict__ out)        // [B,O]
{
    __shared__ SmemU sm;
    const int blk = blockIdx.x;
    const int tid = threadIdx.x;

    // ===================== GEMM phase (3xTF32 mma.sync) =====================
    {
        const int y = (blk < 256) ? ((blk >> 2) * 2) : (((blk - 256) >> 2) * 2 + 1);
        const int xt = blk & 3;
        const int M0 = y * 128;
        const int N0 = xt * 128;

        const int wid  = tid >> 5;
        const int lane = tid & 31;
        const int gid  = lane >> 2;   // 0..7
        const int tig  = lane & 3;    // 0..3
        const int mb = (wid >> 2) * 64;
        const int nb = (wid & 3) * 32;

        const int lm = tid & 127;
        const int lk = tid >> 7;      // 0..1

        const float* Ag = A + (size_t)(M0 + lm) * NC;
        const float* Wg = W + (size_t)(N0 + lm) * NC;

        float acc[4][4][4];
        #pragma unroll
        for (int i = 0; i < 4; ++i)
            #pragma unroll
            for (int j = 0; j < 4; ++j)
                #pragma unroll
                for (int e = 0; e < 4; ++e) acc[i][j][e] = 0.f;

        float4 ra[2], rb[2];
        #pragma unroll
        for (int j = 0; j < 2; ++j) {
            int kq = 2 * j + lk;
            ra[j] = *(const float4*)(Ag + kq * 4);
            rb[j] = *(const float4*)(Wg + kq * 4);
        }
        #pragma unroll
        for (int j = 0; j < 2; ++j) {
            int kq = 2 * j + lk;
            sm.g.sA[0][kq * 4 + 0][lm] = ra[j].x;
            sm.g.sA[0][kq * 4 + 1][lm] = ra[j].y;
            sm.g.sA[0][kq * 4 + 2][lm] = ra[j].z;
            sm.g.sA[0][kq * 4 + 3][lm] = ra[j].w;
            sm.g.sB[0][kq * 4 + 0][lm] = rb[j].x;
            sm.g.sB[0][kq * 4 + 1][lm] = rb[j].y;
            sm.g.sB[0][kq * 4 + 2][lm] = rb[j].z;
            sm.g.sB[0][kq * 4 + 3][lm] = rb[j].w;
        }
        __syncthreads();

        const int NITER = NC / BKI;   // 128
        for (int kc = 0; kc < NITER; ++kc) {
            const int cur = kc & 1;
            const int nxt = cur ^ 1;

            if (kc + 1 < NITER) {
                const int kbase = (kc + 1) * BKI;
                #pragma unroll
                for (int j = 0; j < 2; ++j) {
                    int kq = 2 * j + lk;
                    ra[j] = *(const float4*)(Ag + kbase + kq * 4);
                    rb[j] = *(const float4*)(Wg + kbase + kq * 4);
                }
            }

            #pragma unroll
            for (int ks = 0; ks < 2; ++ks) {
                const int k0 = ks * 8;
                uint32_t bhi[4][2], blo[4][2];
                #pragma unroll
                for (int nt = 0; nt < 4; ++nt) {
                    float b0 = sm.g.sB[cur][k0 + tig][nb + nt * 8 + gid];
                    float b1 = sm.g.sB[cur][k0 + tig + 4][nb + nt * 8 + gid];
                    float h0 = tf32_rna(b0), h1 = tf32_rna(b1);
                    bhi[nt][0] = __float_as_uint(h0);
                    bhi[nt][1] = __float_as_uint(h1);
                    blo[nt][0] = __float_as_uint(tf32_rna(b0 - h0));
                    blo[nt][1] = __float_as_uint(tf32_rna(b1 - h1));
                }
                #pragma unroll
                for (int mt = 0; mt < 4; ++mt) {
                    float a0 = sm.g.sA[cur][k0 + tig][mb + mt * 16 + gid];
                    float a1 = sm.g.sA[cur][k0 + tig][mb + mt * 16 + gid + 8];
                    float a2 = sm.g.sA[cur][k0 + tig + 4][mb + mt * 16 + gid];
                    float a3 = sm.g.sA[cur][k0 + tig + 4][mb + mt * 16 + gid + 8];
                    float h0 = tf32_rna(a0), h1 = tf32_rna(a1);
                    float h2 = tf32_rna(a2), h3 = tf32_rna(a3);
                    uint32_t ahi[4] = { __float_as_uint(h0), __float_as_uint(h1),
                                        __float_as_uint(h2), __float_as_uint(h3) };
                    uint32_t alo[4] = { __float_as_uint(tf32_rna(a0 - h0)),
                                        __float_as_uint(tf32_rna(a1 - h1)),
                                        __float_as_uint(tf32_rna(a2 - h2)),
                                        __float_as_uint(tf32_rna(a3 - h3)) };
                    #pragma unroll
                    for (int nt = 0; nt < 4; ++nt) {
                        mma_tf32(acc[mt][nt], ahi, bhi[nt]);
                        mma_tf32(acc[mt][nt], ahi, blo[nt]);
                        mma_tf32(acc[mt][nt], alo, bhi[nt]);
                    }
                }
            }

            if (kc + 1 < NITER) {
                #pragma unroll
                for (int j = 0; j < 2; ++j) {
                    int kq = 2 * j + lk;
                    sm.g.sA[nxt][kq * 4 + 0][lm] = ra[j].x;
                    sm.g.sA[nxt][kq * 4 + 1][lm] = ra[j].y;
                    sm.g.sA[nxt][kq * 4 + 2][lm] = ra[j].z;
                    sm.g.sA[nxt][kq * 4 + 3][lm] = ra[j].w;
                    sm.g.sB[nxt][kq * 4 + 0][lm] = rb[j].x;
                    sm.g.sB[nxt][kq * 4 + 1][lm] = rb[j].y;
                    sm.g.sB[nxt][kq * 4 + 2][lm] = rb[j].z;
                    sm.g.sB[nxt][kq * 4 + 3][lm] = rb[j].w;
                }
                __syncthreads();
            }
        }

        #pragma unroll
        for (int mt = 0; mt < 4; ++mt) {
            #pragma unroll
            for (int nt = 0; nt < 4; ++nt) {
                int m = M0 + mb + mt * 16 + gid;
                int n = N0 + nb + nt * 8 + tig * 2;
                *(float2*)&g_Iin[(size_t)m * NH + n] =
                    make_float2(acc[mt][nt][0], acc[mt][nt][1]);
                *(float2*)&g_Iin[(size_t)(m + 8) * NH + n] =
                    make_float2(acc[mt][nt][2], acc[mt][nt][3]);
            }
        }

        __threadfence();
        __syncthreads();
        if (tid == 0) atomicAdd(&g_doneY[y], 1);
    }

    if (blk >= NB) return;

    // ============== Speculative SNN (blocks 0..63), with certify ==============
    __syncthreads();

    const int b    = blk;
    const int h    = tid;            // pair (h, h+256)
    const int lane = tid & 31;
    const int warp = tid >> 5;

    #pragma unroll
    for (int o = 0; o < NO; ++o) {
        sm.s.w2t[h * 12 + o]         = w2[o * NH + h];
        sm.s.w2t[(h + 256) * 12 + o] = w2[o * NH + h + 256];
    }
    __syncthreads();

    float v1a = 0.f, v1b = 0.f, recA = 0.f, recB = 0.f;
    float v2 = 0.f, osum = 0.f;
    const float* Iin_b = g_Iin + (size_t)b * NT * NH;

    #pragma unroll 1
    for (int ph = 0; ph < 2; ++ph) {
        if (tid == 0) {
            volatile int* flag = &g_doneY[2 * b + ph];
            while (*flag < 4) __nanosleep(128);
            __threadfence();
        }
        __syncthreads();

        const int t0 = ph * 128, t1 = t0 + 128;
        float iinA = Iin_b[(size_t)t0 * NH + h];
        float iinB = Iin_b[(size_t)t0 * NH + h + 256];

        for (int t = t0; t < t1; ++t) {
            v1a += iinA + recA - LEAKV;
            bool spkA = (v1a >= THRESH);
            // Margin certification: flag neurons whose decision could differ
            if (fabsf(v1a - THRESH) < DELTA) {
                int n = b * NH + h;
                if (atomicExch(&g_flagged[n], 1) == 0) {
                    int i = atomicAdd(&g_fcnt[b], 1);
                    g_flist[b][i] = h;
                }
            }
            if (spkA) v1a -= THRESH;

            v1b += iinB + recB - LEAKV;
            bool spkB = (v1b >= THRESH);
            if (fabsf(v1b - THRESH) < DELTA) {
                int n = b * NH + h + 256;
                if (atomicExch(&g_flagged[n], 1) == 0) {
                    int i = atomicAdd(&g_fcnt[b], 1);
                    g_flist[b][i] = h + 256;
                }
            }
            if (spkB) v1b -= THRESH;

            unsigned mA = __ballot_sync(0xffffffffu, spkA);
            unsigned mB = __ballot_sync(0xffffffffu, spkB);
            if (lane == 0) {
                sm.s.wcnt[warp]     = __popc(mA);
                sm.s.wcnt[8 + warp] = __popc(mB);
                g_spk[b][t][warp]     = mA;
                g_spk[b][t][8 + warp] = mB;
            }
            __syncthreads();
            if (tid == 0) {
                int s = 0;
                #pragma unroll
                for (int w = 0; w < 16; ++w) { sm.s.base[w] = s; s += sm.s.wcnt[w]; }
                sm.s.total = s;
            }
            __syncthreads();
            unsigned lmask = (1u << lane) - 1u;
            if (spkA) sm.s.list[sm.s.base[warp]     + __popc(mA & lmask)] = h;
            if (spkB) sm.s.list[sm.s.base[8 + warp] + __popc(mB & lmask)] = h + 256;
            __syncthreads();

            const int total = sm.s.total;
            if (t + 1 < t1) {
                iinA = Iin_b[(size_t)(t + 1) * NH + h];
                iinB = Iin_b[(size_t)(t + 1) * NH + h + 256];
            }

            recA = 0.f; recB = 0.f;
            #pragma unroll 4
            for (int i = 0; i < total; ++i) {
                const float* row = g_WrecT + (size_t)sm.s.list[i] * NH;
                recA += row[h];
                recB += row[h + 256];
            }

            if (h < NO) {
                float i2 = 0.f;
                #pragma unroll 4
                for (int i = 0; i < total; ++i)
                    i2 += sm.s.w2t[sm.s.list[i] * 12 + h];
                v2 = fmaxf(v2 + i2 - OLEAK, 0.f);
                osum += v2;
            }
            __syncthreads();
        }
    }

    if (h < NO) out[b * NO + h] = osum * (1.0f / (float)NT);
}

// ---------------------------------------------------------------------------
// Recheck: one warp per flagged neuron. Exact fp32 k-ascending i1 chains +
// exact v1 sim against recorded spikes; mismatch -> batch dirty.
// grid = (64 chunks, 64 batches), 256 threads (8 warps).
// ---------------------------------------------------------------------------
__global__ __launch_bounds__(256) void recheck_kernel(
    const float* __restrict__ x, const float* __restrict__ w1)
{
    __shared__ float s_i1[8][NT];
    __shared__ float s_rec[8][NT];

    const int b    = blockIdx.y;
    const int wid  = threadIdx.x >> 5;
    const int lane = threadIdx.x & 31;
    const int slot = blockIdx.x * 8 + wid;

    if (slot >= g_fcnt[b]) return;
    const int h = g_flist[b][slot];

    const float* xb  = x  + (size_t)b * NT * NC;
    const float* w1h = w1 + (size_t)h * NC;

    // Exact i1 chains: 8 timesteps per lane, interleaved for ILP,
    // each chain strictly k-ascending fp32 fma.
    float acc[8];
    #pragma unroll
    for (int j = 0; j < 8; ++j) acc[j] = 0.f;
    const float* xr[8];
    #pragma unroll
    for (int j = 0; j < 8; ++j) xr[j] = xb + (size_t)(j * 32 + lane) * NC;

    for (int k4 = 0; k4 < NC / 4; ++k4) {
        float4 wv = *(const float4*)(w1h + k4 * 4);
        #pragma unroll
        for (int j = 0; j < 8; ++j) {
            float4 xv = *(const float4*)(xr[j] + k4 * 4);
            acc[j] = fmaf(xv.x, wv.x, acc[j]);
            acc[j] = fmaf(xv.y, wv.y, acc[j]);
            acc[j] = fmaf(xv.z, wv.z, acc[j]);
            acc[j] = fmaf(xv.w, wv.w, acc[j]);
        }
    }
    #pragma unroll
    for (int j = 0; j < 8; ++j) s_i1[wid][j * 32 + lane] = acc[j];

    // Exact rec per timestep from recorded spikes (ascending j order)
    #pragma unroll
    for (int j = 0; j < 8; ++j) {
        int t = j * 32 + lane;
        float rec = 0.f;
        if (t > 0) {
            #pragma unroll 4
            for (int w = 0; w < 16; ++w) {
                uint32_t m = g_spk[b][t - 1][w];
                while (m) {
                    int bit = __ffs(m) - 1;
                    rec += g_WrecT[(size_t)(w * 32 + bit) * NH + h];
                    m &= m - 1;
                }
            }
        }
        s_rec[wid][t] = rec;
    }
    __syncwarp();

    if (lane == 0) {
        float v1 = 0.f;
        for (int t = 0; t < NT; ++t) {
            v1 += s_i1[wid][t] + s_rec[wid][t] - LEAKV;
            bool spk = (v1 >= THRESH);
            bool ref = (g_spk[b][t][h >> 5] >> (h & 31)) & 1u;
            if (spk != ref) { g_dirty[b] = 1; break; }
            if (spk) v1 -= THRESH;
        }
    }
}

// ---------------------------------------------------------------------------
// Dirty-batch exact GEMM: 32x128 tiles, 128 threads, 4x8/thread,
// bit-exact fp32 k-ascending chains. grid = (4, 512); early exit if clean.
// ---------------------------------------------------------------------------
__global__ __launch_bounds__(128) void dirty_gemm_kernel(
    const float* __restrict__ A, const float* __restrict__ W)
{
    const int y32 = blockIdx.y;            // 0..511 (32 rows each)
    if (!g_dirty[y32 >> 3]) return;

    __shared__ __align__(16) float sA[8][36];
    __shared__ __align__(16) float sB[8][132];

    const int tid  = threadIdx.x;
    const int M0 = y32 * 32;
    const int N0 = blockIdx.x * 128;

    const int trow = tid >> 4;             // 0..7  -> 4 rows
    const int tcol = tid & 15;             // 0..15 -> 8 cols

    // staging: A 32x8 (each thread float2), B 128x8 (each thread 8 floats)
    const int arow = tid >> 2;             // 0..31
    const int akp  = (tid & 3) * 2;        // 0,2,4,6
    const float* Ag = A + (size_t)(M0 + arow) * NC + akp;
    const float* Wg = W + (size_t)(N0 + tid) * NC;

    float acc[4][8];
    #pragma unroll
    for (int m = 0; m < 4; ++m)
        #pragma unroll
        for (int n = 0; n < 8; ++n) acc[m][n] = 0.f;

    for (int kc = 0; kc < NC / 8; ++kc) {
        float2 av = *(const float2*)(Ag + kc * 8);
        float4 w0 = *(const float4*)(Wg + kc * 8);
        float4 w1v = *(const float4*)(Wg + kc * 8 + 4);
        __syncthreads();
        sA[akp + 0][arow] = av.x;
        sA[akp + 1][arow] = av.y;
        sB[0][tid] = w0.x; sB[1][tid] = w0.y; sB[2][tid] = w0.z; sB[3][tid] = w0.w;
        sB[4][tid] = w1v.x; sB[5][tid] = w1v.y; sB[6][tid] = w1v.z; sB[7][tid] = w1v.w;
        __syncthreads();

        #pragma unroll
        for (int k = 0; k < 8; ++k) {
            float4 a4 = *(const float4*)&sA[k][trow * 4];
            float4 b0 = *(const float4*)&sB[k][tcol * 8];
            float4 b1 = *(const float4*)&sB[k][tcol * 8 + 4];
            float af[4] = {a4.x, a4.y, a4.z, a4.w};
            float bf[8] = {b0.x, b0.y, b0.z, b0.w, b1.x, b1.y, b1.z, b1.w};
            #pragma unroll
            for (int m = 0; m < 4; ++m)
                #pragma unroll
                for (int n = 0; n < 8; ++n)
                    acc[m][n] = fmaf(af[m], bf[n], acc[m][n]);
        }
    }

    float* Cb = g_Iin + (size_t)(M0 + trow * 4) * NH + N0 + tcol * 8;
    #pragma unroll
    for (int m = 0; m < 4; ++m) {
        *(float4*)(Cb + (size_t)m * NH + 0) = make_float4(acc[m][0], acc[m][1], acc[m][2], acc[m][3]);
        *(float4*)(Cb + (size_t)m * NH + 4) = make_float4(acc[m][4], acc[m][5], acc[m][6], acc[m][7]);
    }
}

// ---------------------------------------------------------------------------
// Dirty-batch exact SNN (R8-verbatim arithmetic); early exit if clean.
// ---------------------------------------------------------------------------
__global__ __launch_bounds__(256) void dirty_snn_kernel(
    const float* __restrict__ w2, float* __restrict__ out)
{
    const int b = blockIdx.x;
    if (!g_dirty[b]) return;

    __shared__ int   s_list[NH];
    __shared__ int   s_wcnt[16];
    __shared__ int   s_base[16];
    __shared__ int   s_total;
    __shared__ float s_w2t[NH * 12];

    const int h    = threadIdx.x;
    const int lane = h & 31;
    const int warp = h >> 5;

    #pragma unroll
    for (int o = 0; o < NO; ++o) {
        s_w2t[h * 12 + o]         = w2[o * NH + h];
        s_w2t[(h + 256) * 12 + o] = w2[o * NH + h + 256];
    }
    __syncthreads();

    float v1a = 0.f, v1b = 0.f, recA = 0.f, recB = 0.f;
    float v2 = 0.f, osum = 0.f;
    const float* Iin_b = g_Iin + (size_t)b * NT * NH;

    float iinA = Iin_b[h];
    float iinB = Iin_b[h + 256];

    for (int t = 0; t < NT; ++t) {
        v1a += iinA + recA - LEAKV;
        bool spkA = (v1a >= THRESH);
        if (spkA) v1a -= THRESH;
        v1b += iinB + recB - LEAKV;
        bool spkB = (v1b >= THRESH);
        if (spkB) v1b -= THRESH;

        unsigned mA = __ballot_sync(0xffffffffu, spkA);
        unsigned mB = __ballot_sync(0xffffffffu, spkB);
        if (lane == 0) {
            s_wcnt[warp]     = __popc(mA);
            s_wcnt[8 + warp] = __popc(mB);
        }
        __syncthreads();
        if (h == 0) {
            int s = 0;
            #pragma unroll
            for (int w = 0; w < 16; ++w) { s_base[w] = s; s += s_wcnt[w]; }
            s_total = s;
        }
        __syncthreads();
        unsigned lmask = (1u << lane) - 1u;
        if (spkA) s_list[s_base[warp]     + __popc(mA & lmask)] = h;
        if (spkB) s_list[s_base[8 + warp] + __popc(mB & lmask)] = h + 256;
        __syncthreads();

        const int total = s_total;
        if (t + 1 < NT) {
            iinA = Iin_b[(size_t)(t + 1) * NH + h];
            iinB = Iin_b[(size_t)(t + 1) * NH + h + 256];
        }

        recA = 0.f; recB = 0.f;
        #pragma unroll 4
        for (int i = 0; i < total; ++i) {
            const float* row = g_WrecT + (size_t)s_list[i] * NH;
            recA += row[h];
            recB += row[h + 256];
        }

        if (h < NO) {
            float i2 = 0.f;
            #pragma unroll 4
            for (int i = 0; i < total; ++i)
                i2 += s_w2t[s_list[i] * 12 + h];
            v2 = fmaxf(v2 + i2 - OLEAK, 0.f);
            osum += v2;
        }
        __syncthreads();
    }

    if (h < NO) out[b * NO + h] = osum * (1.0f / (float)NT);
}

// ---------------------------------------------------------------------------
extern "C" void kernel_launch(void* const* d_in, const int* in_sizes, int n_in,
                              void* d_out, int out_size) {
    const float* x     = (const float*)d_in[0];
    const float* w1    = (const float*)d_in[1];
    const float* w_rec = (const float*)d_in[2];
    const float* w2    = (const float*)d_in[3];
    float* out = (float*)d_out;

    prep_kernel<<<(NH * NH + 255) / 256, 256>>>(w_rec);
    fused_kernel<<<512, 256>>>(x, w1, w2, out);
    recheck_kernel<<<dim3(64, 64), 256>>>(x, w1);
    dirty_gemm_kernel<<<dim3(4, 512), 128>>>(x, w1);
    dirty_snn_kernel<<<NB, 256>>>(w2, out);
}

// round 11
// speedup vs baseline: 4.2642x; 4.2642x over previous
#include <cuda_runtime.h>
#include <cstdint>

#define NB 64
#define NT 256
#define NC 2048
#define NH 512
#define NO 11
#define THRESH 1.0f
#define LEAKV  0.003f
#define OLEAK  0.0015f

// Scratch (static device allocations — allowed)
__device__ float g_Iin[NB * NT * NH];      // [b][t][h] = x @ w1^T
__device__ float g_WrecT[NH * NH];         // [j][h] = w_rec[h][j]
__device__ int   g_done64[256];            // per-64-row-subtile counters (->4)

// ---------------------------------------------------------------------------
// Prep: zero flags + transpose w_rec
// ---------------------------------------------------------------------------
__global__ void prep_kernel(const float* __restrict__ w_rec) {
    int idx = blockIdx.x * blockDim.x + threadIdx.x;
    if (idx < 256) g_done64[idx] = 0;
    if (idx < NH * NH) {
        int h = idx / NH, j = idx % NH;
        g_WrecT[j * NH + h] = w_rec[idx];
    }
}

// ---------------------------------------------------------------------------
// Fused kernel, 1024 blocks x 256 threads.
//  GEMM: Iin[M,N] = x[M,K] @ w1[N,K]^T, M=16384 N=512 K=2048.
//   64x128 subtile per CTA, BK=8, 8x4 outputs/thread.
//   BIT-EXACT: each output = one fp32 fmaf chain, k ascending 0..2047.
//   CTA order is time-group-major: tg=0 subtiles of all batches first, ...,
//   tg=3 last -> SNN phases pipeline across batches; tail = one 64-step phase.
//   Publishes g_done64[b*4+tg] (4 x-CTAs per subtile).
//  Blocks 0..63: after their GEMM subtile, morph into SNN batch blk
//   (R8-proven 2-neuron/thread structure, now 4 phases of 64 steps).
// ---------------------------------------------------------------------------
#define BKK 8
#define SASTRIDE 68
#define SBSTRIDE 132

union SmemU {
    struct {
        float sA[2][BKK][SASTRIDE];   // [k][row 0..63]
        float sB[2][BKK][SBSTRIDE];   // [k][row 0..127]
    } g;
    struct {
        int   list[NH];
        int   wcnt[16];
        int   base[16];
        int   total;
        float w2t[NH * 12];
    } s;
};

__global__ __launch_bounds__(256) void fused_kernel(
    const float* __restrict__ A,    // x  [M,K]
    const float* __restrict__ W,    // w1 [N,K]
    const float* __restrict__ w2,   // [O,H]
    float* __restrict__ out)        // [B,O]
{
    __shared__ SmemU sm;
    const int blk = blockIdx.x;
    const int tid = threadIdx.x;

    // ===================== GEMM phase (all 1024 blocks) =====================
    {
        const int K  = NC;
        const int tg = blk >> 8;            // 0..3 time group
        const int bb = (blk & 255) >> 2;    // 0..63 batch
        const int xt = blk & 3;             // 0..3
        const int M0 = bb * 256 + tg * 64;
        const int N0 = xt * 128;
        const int y64 = bb * 4 + tg;

        // Compute mapping: 8 rows x 4 cols per thread
        const int trow = tid >> 5;          // 0..7 (uniform per warp)
        const int tcol = tid & 31;          // 0..31

        // Staging: A 64x8 (float2/thread), B 128x8 (float4/thread)
        const int arow = tid >> 2;          // 0..63
        const int akp  = (tid & 3) * 2;     // 0,2,4,6
        const int brow = tid >> 1;          // 0..127
        const int bkp  = (tid & 1) * 4;     // 0 or 4

        const float* Ag = A + (size_t)(M0 + arow) * K + akp;
        const float* Wg = W + (size_t)(N0 + brow) * K + bkp;

        float acc[8][4];
        #pragma unroll
        for (int m = 0; m < 8; ++m)
            #pragma unroll
            for (int n = 0; n < 4; ++n) acc[m][n] = 0.f;

        float2 av;
        float4 wv;

        // Prologue: chunk 0
        av = *(const float2*)(Ag);
        wv = *(const float4*)(Wg);
        sm.g.sA[0][akp + 0][arow] = av.x;
        sm.g.sA[0][akp + 1][arow] = av.y;
        sm.g.sB[0][bkp + 0][brow] = wv.x;
        sm.g.sB[0][bkp + 1][brow] = wv.y;
        sm.g.sB[0][bkp + 2][brow] = wv.z;
        sm.g.sB[0][bkp + 3][brow] = wv.w;
        __syncthreads();

        const int NITER = K / BKK;   // 256
        for (int kc = 0; kc < NITER; ++kc) {
            const int cur = kc & 1;
            const int nxt = cur ^ 1;

            if (kc + 1 < NITER) {
                av = *(const float2*)(Ag + (kc + 1) * BKK);
                wv = *(const float4*)(Wg + (kc + 1) * BKK);
            }

            #pragma unroll
            for (int k = 0; k < BKK; ++k) {
                float4 a03 = *(const float4*)&sm.g.sA[cur][k][trow * 8 + 0];
                float4 a47 = *(const float4*)&sm.g.sA[cur][k][trow * 8 + 4];
                float4 b4  = *(const float4*)&sm.g.sB[cur][k][tcol * 4];
                float af[8] = {a03.x, a03.y, a03.z, a03.w,
                               a47.x, a47.y, a47.z, a47.w};
                float bf[4] = {b4.x, b4.y, b4.z, b4.w};
                #pragma unroll
                for (int m = 0; m < 8; ++m)
                    #pragma unroll
                    for (int n = 0; n < 4; ++n)
                        acc[m][n] = fmaf(af[m], bf[n], acc[m][n]);
            }

            if (kc + 1 < NITER) {
                sm.g.sA[nxt][akp + 0][arow] = av.x;
                sm.g.sA[nxt][akp + 1][arow] = av.y;
                sm.g.sB[nxt][bkp + 0][brow] = wv.x;
                sm.g.sB[nxt][bkp + 1][brow] = wv.y;
                sm.g.sB[nxt][bkp + 2][brow] = wv.z;
                sm.g.sB[nxt][bkp + 3][brow] = wv.w;
                __syncthreads();
            }
        }

        // Epilogue: float4 stores, coalesced across the warp
        float* Cb = g_Iin + ((size_t)M0 + trow * 8) * NH + N0 + tcol * 4;
        #pragma unroll
        for (int m = 0; m < 8; ++m) {
            *(float4*)(Cb + (size_t)m * NH) =
                make_float4(acc[m][0], acc[m][1], acc[m][2], acc[m][3]);
        }

        // Publish subtile completion
        __threadfence();
        __syncthreads();
        if (tid == 0) atomicAdd(&g_done64[y64], 1);
    }

    if (blk >= NB) return;

    // ===================== SNN phase (blocks 0..63) =====================
    __syncthreads();   // smem reuse barrier

    const int b    = blk;
    const int h    = tid;            // neuron pair (h, h+256)
    const int lane = tid & 31;
    const int warp = tid >> 5;       // 0..7

    #pragma unroll
    for (int o = 0; o < NO; ++o) {
        sm.s.w2t[h * 12 + o]          = w2[o * NH + h];
        sm.s.w2t[(h + 256) * 12 + o]  = w2[o * NH + h + 256];
    }
    __syncthreads();

    float v1a = 0.f, v1b = 0.f, recA = 0.f, recB = 0.f;
    float v2 = 0.f, osum = 0.f;
    const float* Iin_b = g_Iin + (size_t)b * NT * NH;

    #pragma unroll 1
    for (int ph = 0; ph < 4; ++ph) {
        // Wait for this 64-step group's GEMM subtile (4 x-CTAs)
        if (tid == 0) {
            volatile int* flag = &g_done64[b * 4 + ph];
            while (*flag < 4) __nanosleep(128);
            __threadfence();
        }
        __syncthreads();

        const int t0 = ph * 64, t1 = t0 + 64;
        float iinA = Iin_b[(size_t)t0 * NH + h];
        float iinB = Iin_b[(size_t)t0 * NH + h + 256];

        for (int t = t0; t < t1; ++t) {
            // LIF updates for both neurons (same math/order as R1/R8)
            v1a += iinA + recA - LEAKV;
            bool spkA = (v1a >= THRESH);
            if (spkA) v1a -= THRESH;
            v1b += iinB + recB - LEAKV;
            bool spkB = (v1b >= THRESH);
            if (spkB) v1b -= THRESH;

            unsigned mA = __ballot_sync(0xffffffffu, spkA);
            unsigned mB = __ballot_sync(0xffffffffu, spkB);
            if (lane == 0) {
                sm.s.wcnt[warp]     = __popc(mA);
                sm.s.wcnt[8 + warp] = __popc(mB);
            }
            __syncthreads();
            if (tid == 0) {
                int s = 0;
                #pragma unroll
                for (int w = 0; w < 16; ++w) { sm.s.base[w] = s; s += sm.s.wcnt[w]; }
                sm.s.total = s;
            }
            __syncthreads();
            // list content/order identical to R1: h ascending 0..511
            unsigned lm = (1u << lane) - 1u;
            if (spkA) sm.s.list[sm.s.base[warp]     + __popc(mA & lm)] = h;
            if (spkB) sm.s.list[sm.s.base[8 + warp] + __popc(mB & lm)] = h + 256;
            __syncthreads();

            const int total = sm.s.total;
            if (t + 1 < t1) {
                iinA = Iin_b[(size_t)(t + 1) * NH + h];
                iinB = Iin_b[(size_t)(t + 1) * NH + h + 256];
            }

            recA = 0.f; recB = 0.f;
            #pragma unroll 4
            for (int i = 0; i < total; ++i) {
                const float* row = g_WrecT + (size_t)sm.s.list[i] * NH;
                recA += row[h];
                recB += row[h + 256];
            }

            if (h < NO) {
                float i2 = 0.f;
                #pragma unroll 4
                for (int i = 0; i < total; ++i)
                    i2 += sm.s.w2t[sm.s.list[i] * 12 + h];
                v2 = fmaxf(v2 + i2 - OLEAK, 0.f);
                osum += v2;
            }
            __syncthreads();
        }
    }

    if (h < NO) out[b * NO + h] = osum * (1.0f / (float)NT);
}

// ---------------------------------------------------------------------------
extern "C" void kernel_launch(void* const* d_in, const int* in_sizes, int n_in,
                              void* d_out, int out_size) {
    const float* x     = (const float*)d_in[0];
    const float* w1    = (const float*)d_in[1];
    const float* w_rec = (const float*)d_in[2];
    const float* w2    = (const float*)d_in[3];
    float* out = (float*)d_out;

    prep_kernel<<<(NH * NH + 255) / 256, 256>>>(w_rec);
    fused_kernel<<<1024, 256>>>(x, w1, w2, out);
}